// round 7
// baseline (speedup 1.0000x reference)
#include <cuda_runtime.h>
#include <cuda_fp16.h>
#include <cstdint>
#include <cstddef>

// R7: persistent LSTM on mma.sync (m16n8k16 fp16, fp32 accum).
// vs R6: (1) global 128-CTA barrier replaced by 8 independent 16-CTA group
// barriers (dependency is block-diagonal in the M tiles); (2) h-load latency
// hidden under the x-part MMAs (ks 0..7 need no h).
// 128 CTAs = 8 M-tiles(64 rows) x 16 N-tiles(64 cols = 16 jl x 4 gates).
// Weights in registers (96 b32/thread). A=[x_t|h] fp16 in 48KB smem.

#define SEQ   512
#define BATCH 512
#define DIM   128
#define HID   256
#define G4    1024
#define NCTA  128
#define NTHR  256
#define NKS   24             // K = 384 = 24 x 16
#define NGRP  16             // CTAs per barrier group (one M tile)

// ---- persistent device scratch ----
__device__ __align__(16) __half g_h16[2][BATCH * HID];
__device__ __align__(128) unsigned long long g_bar_grp[8][16]; // 128B apart

__device__ __forceinline__ uint32_t smem_u32(const void* p) {
    uint32_t a;
    asm("{ .reg .u64 t; cvta.to.shared.u64 t, %1; cvt.u32.u64 %0, t; }"
        : "=r"(a) : "l"(p));
    return a;
}
__device__ __forceinline__ void ldsm4(uint32_t a[4], uint32_t addr) {
    asm volatile("ldmatrix.sync.aligned.m8n8.x4.shared.b16 {%0,%1,%2,%3}, [%4];"
                 : "=r"(a[0]), "=r"(a[1]), "=r"(a[2]), "=r"(a[3]) : "r"(addr));
}
__device__ __forceinline__ void mma16816(float c[4], const uint32_t a[4],
                                         uint32_t b0, uint32_t b1) {
    asm volatile(
        "mma.sync.aligned.m16n8k16.row.col.f32.f16.f16.f32 "
        "{%0,%1,%2,%3}, {%4,%5,%6,%7}, {%8,%9}, {%0,%1,%2,%3};"
        : "+f"(c[0]), "+f"(c[1]), "+f"(c[2]), "+f"(c[3])
        : "r"(a[0]), "r"(a[1]), "r"(a[2]), "r"(a[3]), "r"(b0), "r"(b1));
}

__device__ __forceinline__ float sigf(float x) {
    return __fdividef(1.0f, 1.0f + __expf(-x));
}
__device__ __forceinline__ float tanhf_fast(float x) {
    return 1.0f - __fdividef(2.0f, 1.0f + __expf(2.0f * x));
}

// A-tile swizzled offset: block per kstep = 64 rows x 32B.
__device__ __forceinline__ uint32_t a_phys(int ks, int row, int kh /*0,1*/) {
    return (uint32_t)(ks * 2048 + row * 32 + ((kh << 4) ^ ((row & 4) << 2)));
}

// Monotonic per-group ticket barrier (graph-replay-safe; 16 CTAs).
__device__ __forceinline__ void group_barrier(int grp) {
    __syncthreads();
    if (threadIdx.x == 0) {
        __threadfence();
        unsigned long long* ctr = &g_bar_grp[grp][0];
        unsigned long long t = atomicAdd(ctr, 1ULL) + 1ULL;
        unsigned long long target =
            ((t + (unsigned long long)NGRP - 1ULL) / NGRP) * (unsigned long long)NGRP;
        unsigned long long v;
        do {
            asm volatile("ld.acquire.gpu.u64 %0, [%1];" : "=l"(v) : "l"(ctr) : "memory");
        } while (v < target);
    }
    __syncthreads();
}

__global__ void __launch_bounds__(NTHR, 1)
lstm_hmma(const float* __restrict__ x,  const float* __restrict__ Wx,
          const float* __restrict__ Wh, const float* __restrict__ bv,
          const float* __restrict__ Wd, const float* __restrict__ bd,
          float* __restrict__ out)
{
    __shared__ __align__(1024) char sA[NKS * 2048];   // 48 KB: [x_t | h] fp16
    const uint32_t sA_u = smem_u32(sA);

    const int tid  = threadIdx.x;
    const int cta  = blockIdx.x;
    const int warp = tid >> 5, lane = tid & 31;
    const int grp = cta >> 4;           // M-tile group (16 CTAs)
    const int r0 = grp * 64;            // M tile: 64 batch rows
    const int j0 = (cta & 15) * 16;     // 16 hidden cols
    const int wM = warp & 1;            // 2-way M split (32 rows)
    const int wN = warp >> 1;           // 4-way N split (16 n-cols)

    // ---- one-time: B fragments into registers ----
    uint32_t bfr[NKS][2][2];
    {
        #pragma unroll
        for (int ks = 0; ks < NKS; ++ks) {
            #pragma unroll
            for (int nb = 0; nb < 2; ++nb) {
                int n = wN * 16 + nb * 8 + (lane >> 2);
                int col = (n & 3) * HID + j0 + (n >> 2);
                int k0 = ks * 16 + (lane & 3) * 2;
                float w0, w1, w2, w3;
                if (k0 < DIM) {
                    w0 = Wx[(size_t)k0 * G4 + col];
                    w1 = Wx[(size_t)(k0 + 1) * G4 + col];
                } else {
                    w0 = Wh[(size_t)(k0 - DIM) * G4 + col];
                    w1 = Wh[(size_t)(k0 - DIM + 1) * G4 + col];
                }
                int k8 = k0 + 8;
                if (k8 < DIM) {
                    w2 = Wx[(size_t)k8 * G4 + col];
                    w3 = Wx[(size_t)(k8 + 1) * G4 + col];
                } else {
                    w2 = Wh[(size_t)(k8 - DIM) * G4 + col];
                    w3 = Wh[(size_t)(k8 - DIM + 1) * G4 + col];
                }
                union { __half2 h; uint32_t u; } p0, p1;
                p0.h = __floats2half2_rn(w0, w1);
                p1.h = __floats2half2_rn(w2, w3);
                bfr[ks][nb][0] = p0.u;
                bfr[ks][nb][1] = p1.u;
            }
        }
    }

    // zero h buffer 0 (group-local range: cta*2KB covers group rows)
    ((uint2*)g_h16[0])[cta * NTHR + tid] = make_uint2(0u, 0u);

    // epilogue geometry: pair (lane, lane^1) shares jl; even=mb0, odd=mb1
    const int myOdd = lane & 1;
    const int rA = wM * 32 + myOdd * 16 + (lane >> 2);
    const int jA = (lane & 3) >> 1;
    float bI[2], bF[2], bG[2], bO[2];
    #pragma unroll
    for (int nb = 0; nb < 2; ++nb) {
        int j = j0 + wN * 4 + nb * 2 + jA;
        bI[nb] = bv[j];
        bF[nb] = bv[HID + j];
        bG[nb] = bv[2 * HID + j];
        bO[nb] = bv[3 * HID + j];
    }
    float cst[4] = {0.f, 0.f, 0.f, 0.f};

    // A-loader coords
    const int xrow = tid >> 2, xkb = (tid & 3) * 32;     // x: 32 halfs/thread
    const int hkb  = (tid & 3) * 64;                     // h: 64 halfs/thread

    // ldmatrix per-thread addr bases (two m16 tiles)
    const int lrow = lane & 15, lkh = lane >> 4;
    uint32_t lds0 = sA_u + a_phys(0, wM * 32 + lrow, lkh);
    uint32_t lds1 = sA_u + a_phys(0, wM * 32 + 16 + lrow, lkh);

    // ---- prologue: stage x(0) into smem ----
    {
        const float* xp = x + ((size_t)(r0 + xrow) * SEQ + 0) * DIM + xkb;
        #pragma unroll
        for (int c2 = 0; c2 < 4; ++c2) {
            float4 v0 = *(const float4*)(xp + c2 * 8);
            float4 v1 = *(const float4*)(xp + c2 * 8 + 4);
            union { __half2 h; uint32_t u; } q0, q1, q2, q3;
            q0.h = __floats2half2_rn(v0.x, v0.y);
            q1.h = __floats2half2_rn(v0.z, v0.w);
            q2.h = __floats2half2_rn(v1.x, v1.y);
            q3.h = __floats2half2_rn(v1.z, v1.w);
            int k = xkb + c2 * 8;
            *(uint4*)(sA + a_phys(k >> 4, xrow, (k >> 3) & 1)) =
                make_uint4(q0.u, q1.u, q2.u, q3.u);
        }
    }

    group_barrier(grp);   // h0 zero visible within group; x(0) staged

    for (int s = 0; s < SEQ; ++s) {
        // -- issue h(s) loads FIRST (L1-bypass); latency hides under x-MMAs
        const __half* hp = g_h16[s & 1];
        const uint4* hsrc = (const uint4*)(hp + (size_t)(r0 + xrow) * HID + hkb);
        uint4 hr[8];
        #pragma unroll
        for (int c = 0; c < 8; ++c) hr[c] = __ldcv(hsrc + c);

        // -- x-part MMAs (ks 0..7): x(s) already staged in sA
        float acc[2][2][4];
        #pragma unroll
        for (int mb = 0; mb < 2; ++mb)
            #pragma unroll
            for (int nb = 0; nb < 2; ++nb)
                #pragma unroll
                for (int k = 0; k < 4; ++k) acc[mb][nb][k] = 0.f;

        #pragma unroll
        for (int ks = 0; ks < 8; ++ks) {
            uint32_t am0[4], am1[4];
            ldsm4(am0, lds0 + ks * 2048);
            ldsm4(am1, lds1 + ks * 2048);
            mma16816(acc[0][0], am0, bfr[ks][0][0], bfr[ks][0][1]);
            mma16816(acc[0][1], am0, bfr[ks][1][0], bfr[ks][1][1]);
            mma16816(acc[1][0], am1, bfr[ks][0][0], bfr[ks][0][1]);
            mma16816(acc[1][1], am1, bfr[ks][1][0], bfr[ks][1][1]);
        }

        // -- stage h into sA
        #pragma unroll
        for (int c = 0; c < 8; ++c) {
            int kg = DIM + hkb + c * 8;
            *(uint4*)(sA + a_phys(kg >> 4, xrow, (kg >> 3) & 1)) = hr[c];
        }
        __syncthreads();

        // -- h-part MMAs (ks 8..23)
        #pragma unroll
        for (int ks = 8; ks < NKS; ++ks) {
            uint32_t am0[4], am1[4];
            ldsm4(am0, lds0 + ks * 2048);
            ldsm4(am1, lds1 + ks * 2048);
            mma16816(acc[0][0], am0, bfr[ks][0][0], bfr[ks][0][1]);
            mma16816(acc[0][1], am0, bfr[ks][1][0], bfr[ks][1][1]);
            mma16816(acc[1][0], am1, bfr[ks][0][0], bfr[ks][0][1]);
            mma16816(acc[1][1], am1, bfr[ks][1][0], bfr[ks][1][1]);
        }

        // -- pairwise gate exchange: even lanes own (i,f), odd own (g,o)
        float zif[2][4], zgo[2][4];
        #pragma unroll
        for (int nb = 0; nb < 2; ++nb)
            #pragma unroll
            for (int k = 0; k < 4; ++k) {
                float s0 = __shfl_xor_sync(0xffffffffu, acc[0][nb][k], 1);
                float s1 = __shfl_xor_sync(0xffffffffu, acc[1][nb][k], 1);
                zif[nb][k] = myOdd ? s1 : acc[0][nb][k];
                zgo[nb][k] = myOdd ? acc[1][nb][k] : s0;
            }

        // -- cell update + h(s+1) store (fp16)
        __half* hn = g_h16[(s + 1) & 1];
        #pragma unroll
        for (int nb = 0; nb < 2; ++nb) {
            int j = j0 + wN * 4 + nb * 2 + jA;
            float i0 = sigf(zif[nb][0] + bI[nb]);
            float f0 = sigf(zif[nb][1] + bF[nb]);
            float g0 = tanhf_fast(zgo[nb][0] + bG[nb]);
            float o0 = sigf(zgo[nb][1] + bO[nb]);
            float i1 = sigf(zif[nb][2] + bI[nb]);
            float f1 = sigf(zif[nb][3] + bF[nb]);
            float g1 = tanhf_fast(zgo[nb][2] + bG[nb]);
            float o1 = sigf(zgo[nb][3] + bO[nb]);
            cst[nb * 2 + 0] = f0 * cst[nb * 2 + 0] + i0 * g0;
            cst[nb * 2 + 1] = f1 * cst[nb * 2 + 1] + i1 * g1;
            hn[(size_t)(r0 + rA) * HID + j] =
                __float2half_rn(o0 * tanhf_fast(cst[nb * 2 + 0]));
            hn[(size_t)(r0 + rA + 8) * HID + j] =
                __float2half_rn(o1 * tanhf_fast(cst[nb * 2 + 1]));
        }

        // -- stage x(s+1) (barrier skew hides the LDG latency)
        __syncthreads();                      // all warps done reading sA
        if (s + 1 < SEQ) {
            const float* xp = x + ((size_t)(r0 + xrow) * SEQ + (s + 1)) * DIM + xkb;
            #pragma unroll
            for (int c2 = 0; c2 < 4; ++c2) {
                float4 v0 = *(const float4*)(xp + c2 * 8);
                float4 v1 = *(const float4*)(xp + c2 * 8 + 4);
                union { __half2 h; uint32_t u; } q0, q1, q2, q3;
                q0.h = __floats2half2_rn(v0.x, v0.y);
                q1.h = __floats2half2_rn(v0.z, v0.w);
                q2.h = __floats2half2_rn(v1.x, v1.y);
                q3.h = __floats2half2_rn(v1.z, v1.w);
                int k = xkb + c2 * 8;
                *(uint4*)(sA + a_phys(k >> 4, xrow, (k >> 3) & 1)) =
                    make_uint4(q0.u, q1.u, q2.u, q3.u);
            }
        }

        group_barrier(grp);
    }

    // ---- classifier + softmax: rows are group-local ----
    if (warp < 4) {
        const int row = cta * 4 + warp;
        const __half* hf = g_h16[0];
        float acc10[10];
        #pragma unroll
        for (int c = 0; c < 10; ++c) acc10[c] = 0.f;
        uint4 hv = __ldcv((const uint4*)(hf + (size_t)row * HID + lane * 8));
        const __half* hvh = (const __half*)&hv;
        #pragma unroll
        for (int u = 0; u < 8; ++u) {
            float h = __half2float(hvh[u]);
            const float* wd = Wd + (size_t)(lane * 8 + u) * 10;
            #pragma unroll
            for (int c = 0; c < 10; ++c) acc10[c] += h * wd[c];
        }
        #pragma unroll
        for (int off = 16; off > 0; off >>= 1) {
            #pragma unroll
            for (int c = 0; c < 10; ++c)
                acc10[c] += __shfl_down_sync(0xffffffffu, acc10[c], off);
        }
        if (lane == 0) {
            float m = -3.0e38f;
            #pragma unroll
            for (int c = 0; c < 10; ++c) { acc10[c] += bd[c]; m = fmaxf(m, acc10[c]); }
            float ssum = 0.f;
            #pragma unroll
            for (int c = 0; c < 10; ++c) { acc10[c] = __expf(acc10[c] - m); ssum += acc10[c]; }
            float inv = 1.0f / ssum;
            #pragma unroll
            for (int c = 0; c < 10; ++c) out[(size_t)row * 10 + c] = acc10[c] * inv;
        }
    }
}

extern "C" void kernel_launch(void* const* d_in, const int* in_sizes, int n_in,
                              void* d_out, int out_size) {
    const float* x  = (const float*)d_in[0];
    const float* Wx = (const float*)d_in[1];
    const float* Wh = (const float*)d_in[2];
    const float* b  = (const float*)d_in[3];
    const float* Wd = (const float*)d_in[4];
    const float* bd = (const float*)d_in[5];
    (void)in_sizes; (void)n_in; (void)out_size;
    lstm_hmma<<<NCTA, NTHR>>>(x, Wx, Wh, b, Wd, bd, (float*)d_out);
}

// round 8
// speedup vs baseline: 1.0992x; 1.0992x over previous
#include <cuda_runtime.h>
#include <cuda_fp16.h>
#include <cstdint>
#include <cstddef>

// R8: persistent LSTM on mma.sync m16n8k16 with FP16 ACCUMULATION (promoted
// to fp32 every 4 k-steps) -- tests the 2x f16-acc rate hypothesis; the R6/R7
// data shows the kernel is HMMA-issue-throughput-bound (~256 FLOP/cyc/SM).
// Also: tanh.approx epilogue, split arrive/wait group barrier (x staged in
// the window). 128 CTAs = 8 M-groups(64 rows) x 16 N-tiles(16 jl x 4 gates).

#define SEQ   512
#define BATCH 512
#define DIM   128
#define HID   256
#define G4    1024
#define NCTA  128
#define NTHR  256
#define NKS   24             // K = 384 = 24 x 16
#define NGRP  16             // CTAs per barrier group (one M tile)

// ---- persistent device scratch ----
__device__ __align__(16) __half g_h16[2][BATCH * HID];
__device__ __align__(128) unsigned long long g_bar_grp[8][16]; // 128B apart

__device__ __forceinline__ uint32_t smem_u32(const void* p) {
    uint32_t a;
    asm("{ .reg .u64 t; cvta.to.shared.u64 t, %1; cvt.u32.u64 %0, t; }"
        : "=r"(a) : "l"(p));
    return a;
}
__device__ __forceinline__ void ldsm4(uint32_t a[4], uint32_t addr) {
    asm volatile("ldmatrix.sync.aligned.m8n8.x4.shared.b16 {%0,%1,%2,%3}, [%4];"
                 : "=r"(a[0]), "=r"(a[1]), "=r"(a[2]), "=r"(a[3]) : "r"(addr));
}
// f16-accumulate MMA: D(f16x2 in 2 regs) = A*B + D
__device__ __forceinline__ void mma_f16acc(uint32_t c[2], const uint32_t a[4],
                                           uint32_t b0, uint32_t b1) {
    asm volatile(
        "mma.sync.aligned.m16n8k16.row.col.f16.f16.f16.f16 "
        "{%0,%1}, {%2,%3,%4,%5}, {%6,%7}, {%0,%1};"
        : "+r"(c[0]), "+r"(c[1])
        : "r"(a[0]), "r"(a[1]), "r"(a[2]), "r"(a[3]), "r"(b0), "r"(b1));
}
// promote f16 partial accumulators into fp32 masters, zero the f16 regs
__device__ __forceinline__ void promote(float acc[4], uint32_t hc[2]) {
    float2 lo = __half22float2(*reinterpret_cast<__half2*>(&hc[0]));
    float2 hi = __half22float2(*reinterpret_cast<__half2*>(&hc[1]));
    acc[0] += lo.x; acc[1] += lo.y; acc[2] += hi.x; acc[3] += hi.y;
    hc[0] = 0u; hc[1] = 0u;
}

__device__ __forceinline__ float tanh_mufu(float x) {
    float y;
    asm("tanh.approx.f32 %0, %1;" : "=f"(y) : "f"(x));
    return y;
}
__device__ __forceinline__ float sig_mufu(float x) {
    return fmaf(0.5f, tanh_mufu(0.5f * x), 0.5f);
}

// A-tile swizzled offset: block per kstep = 64 rows x 32B.
__device__ __forceinline__ uint32_t a_phys(int ks, int row, int kh /*0,1*/) {
    return (uint32_t)(ks * 2048 + row * 32 + ((kh << 4) ^ ((row & 4) << 2)));
}

// Monotonic per-group ticket barrier (graph-replay-safe; 16 CTAs).
__device__ __forceinline__ void group_barrier(int grp) {
    __syncthreads();
    if (threadIdx.x == 0) {
        __threadfence();
        unsigned long long* ctr = &g_bar_grp[grp][0];
        unsigned long long t = atomicAdd(ctr, 1ULL) + 1ULL;
        unsigned long long target =
            ((t + (unsigned long long)NGRP - 1ULL) / NGRP) * (unsigned long long)NGRP;
        unsigned long long v;
        do {
            asm volatile("ld.acquire.gpu.u64 %0, [%1];" : "=l"(v) : "l"(ctr) : "memory");
        } while (v < target);
    }
    __syncthreads();
}

__global__ void __launch_bounds__(NTHR, 1)
lstm_hmma(const float* __restrict__ x,  const float* __restrict__ Wx,
          const float* __restrict__ Wh, const float* __restrict__ bv,
          const float* __restrict__ Wd, const float* __restrict__ bd,
          float* __restrict__ out)
{
    __shared__ __align__(1024) char sA[NKS * 2048];   // 48 KB: [x_t | h] fp16
    const uint32_t sA_u = smem_u32(sA);

    const int tid  = threadIdx.x;
    const int cta  = blockIdx.x;
    const int warp = tid >> 5, lane = tid & 31;
    const int grp = cta >> 4;           // M-tile group (16 CTAs)
    const int r0 = grp * 64;            // M tile: 64 batch rows
    const int j0 = (cta & 15) * 16;     // 16 hidden cols
    const int wM = warp & 1;            // 2-way M split (32 rows)
    const int wN = warp >> 1;           // 4-way N split (16 n-cols)
    unsigned long long* const bar_ctr = &g_bar_grp[grp][0];

    // ---- one-time: B fragments into registers ----
    uint32_t bfr[NKS][2][2];
    {
        #pragma unroll
        for (int ks = 0; ks < NKS; ++ks) {
            #pragma unroll
            for (int nb = 0; nb < 2; ++nb) {
                int n = wN * 16 + nb * 8 + (lane >> 2);
                int col = (n & 3) * HID + j0 + (n >> 2);
                int k0 = ks * 16 + (lane & 3) * 2;
                float w0, w1, w2, w3;
                if (k0 < DIM) {
                    w0 = Wx[(size_t)k0 * G4 + col];
                    w1 = Wx[(size_t)(k0 + 1) * G4 + col];
                } else {
                    w0 = Wh[(size_t)(k0 - DIM) * G4 + col];
                    w1 = Wh[(size_t)(k0 - DIM + 1) * G4 + col];
                }
                int k8 = k0 + 8;
                if (k8 < DIM) {
                    w2 = Wx[(size_t)k8 * G4 + col];
                    w3 = Wx[(size_t)(k8 + 1) * G4 + col];
                } else {
                    w2 = Wh[(size_t)(k8 - DIM) * G4 + col];
                    w3 = Wh[(size_t)(k8 - DIM + 1) * G4 + col];
                }
                union { __half2 h; uint32_t u; } p0, p1;
                p0.h = __floats2half2_rn(w0, w1);
                p1.h = __floats2half2_rn(w2, w3);
                bfr[ks][nb][0] = p0.u;
                bfr[ks][nb][1] = p1.u;
            }
        }
    }

    // zero h buffer 0 (group-local range)
    ((uint2*)g_h16[0])[cta * NTHR + tid] = make_uint2(0u, 0u);

    // epilogue geometry
    const int myOdd = lane & 1;
    const int rA = wM * 32 + myOdd * 16 + (lane >> 2);
    const int jA = (lane & 3) >> 1;
    float bI[2], bF[2], bG[2], bO[2];
    #pragma unroll
    for (int nb = 0; nb < 2; ++nb) {
        int j = j0 + wN * 4 + nb * 2 + jA;
        bI[nb] = bv[j];
        bF[nb] = bv[HID + j];
        bG[nb] = bv[2 * HID + j];
        bO[nb] = bv[3 * HID + j];
    }
    float cst[4] = {0.f, 0.f, 0.f, 0.f};

    // loader coords
    const int xrow = tid >> 2, xkb = (tid & 3) * 32;
    const int hkb  = (tid & 3) * 64;

    const int lrow = lane & 15, lkh = lane >> 4;
    uint32_t lds0 = sA_u + a_phys(0, wM * 32 + lrow, lkh);
    uint32_t lds1 = sA_u + a_phys(0, wM * 32 + 16 + lrow, lkh);

    // ---- prologue: stage x(0) ----
    {
        const float* xp = x + ((size_t)(r0 + xrow) * SEQ + 0) * DIM + xkb;
        #pragma unroll
        for (int c2 = 0; c2 < 4; ++c2) {
            float4 v0 = *(const float4*)(xp + c2 * 8);
            float4 v1 = *(const float4*)(xp + c2 * 8 + 4);
            union { __half2 h; uint32_t u; } q0, q1, q2, q3;
            q0.h = __floats2half2_rn(v0.x, v0.y);
            q1.h = __floats2half2_rn(v0.z, v0.w);
            q2.h = __floats2half2_rn(v1.x, v1.y);
            q3.h = __floats2half2_rn(v1.z, v1.w);
            int k = xkb + c2 * 8;
            *(uint4*)(sA + a_phys(k >> 4, xrow, (k >> 3) & 1)) =
                make_uint4(q0.u, q1.u, q2.u, q3.u);
        }
    }

    group_barrier(grp);   // h0 zero visible within group; x(0) staged

    for (int s = 0; s < SEQ; ++s) {
        // -- issue h(s) loads first (L1-bypass); hide under x-part MMAs
        const __half* hp = g_h16[s & 1];
        const uint4* hsrc = (const uint4*)(hp + (size_t)(r0 + xrow) * HID + hkb);
        uint4 hr[8];
        #pragma unroll
        for (int c = 0; c < 8; ++c) hr[c] = __ldcv(hsrc + c);

        // fp32 master accumulators + f16 partials
        float acc[2][2][4];
        uint32_t hc[2][2][2];
        #pragma unroll
        for (int mb = 0; mb < 2; ++mb)
            #pragma unroll
            for (int nb = 0; nb < 2; ++nb) {
                #pragma unroll
                for (int k = 0; k < 4; ++k) acc[mb][nb][k] = 0.f;
                hc[mb][nb][0] = 0u; hc[mb][nb][1] = 0u;
            }

        // -- x-part MMAs (ks 0..7), promote every 4 k-steps
        #pragma unroll
        for (int g4 = 0; g4 < 2; ++g4) {
            #pragma unroll
            for (int kq = 0; kq < 4; ++kq) {
                int ks = g4 * 4 + kq;
                uint32_t am0[4], am1[4];
                ldsm4(am0, lds0 + ks * 2048);
                ldsm4(am1, lds1 + ks * 2048);
                mma_f16acc(hc[0][0], am0, bfr[ks][0][0], bfr[ks][0][1]);
                mma_f16acc(hc[0][1], am0, bfr[ks][1][0], bfr[ks][1][1]);
                mma_f16acc(hc[1][0], am1, bfr[ks][0][0], bfr[ks][0][1]);
                mma_f16acc(hc[1][1], am1, bfr[ks][1][0], bfr[ks][1][1]);
            }
            promote(acc[0][0], hc[0][0]); promote(acc[0][1], hc[0][1]);
            promote(acc[1][0], hc[1][0]); promote(acc[1][1], hc[1][1]);
        }

        // -- stage h into sA
        #pragma unroll
        for (int c = 0; c < 8; ++c) {
            int kg = DIM + hkb + c * 8;
            *(uint4*)(sA + a_phys(kg >> 4, xrow, (kg >> 3) & 1)) = hr[c];
        }
        __syncthreads();

        // -- h-part MMAs (ks 8..23), promote every 4 k-steps
        #pragma unroll
        for (int g4 = 0; g4 < 4; ++g4) {
            #pragma unroll
            for (int kq = 0; kq < 4; ++kq) {
                int ks = 8 + g4 * 4 + kq;
                uint32_t am0[4], am1[4];
                ldsm4(am0, lds0 + ks * 2048);
                ldsm4(am1, lds1 + ks * 2048);
                mma_f16acc(hc[0][0], am0, bfr[ks][0][0], bfr[ks][0][1]);
                mma_f16acc(hc[0][1], am0, bfr[ks][1][0], bfr[ks][1][1]);
                mma_f16acc(hc[1][0], am1, bfr[ks][0][0], bfr[ks][0][1]);
                mma_f16acc(hc[1][1], am1, bfr[ks][1][0], bfr[ks][1][1]);
            }
            promote(acc[0][0], hc[0][0]); promote(acc[0][1], hc[0][1]);
            promote(acc[1][0], hc[1][0]); promote(acc[1][1], hc[1][1]);
        }

        // -- pairwise gate exchange: even lanes own (i,f), odd own (g,o)
        float zif[2][4], zgo[2][4];
        #pragma unroll
        for (int nb = 0; nb < 2; ++nb)
            #pragma unroll
            for (int k = 0; k < 4; ++k) {
                float s0 = __shfl_xor_sync(0xffffffffu, acc[0][nb][k], 1);
                float s1 = __shfl_xor_sync(0xffffffffu, acc[1][nb][k], 1);
                zif[nb][k] = myOdd ? s1 : acc[0][nb][k];
                zgo[nb][k] = myOdd ? acc[1][nb][k] : s0;
            }

        // -- cell update + h(s+1) store (fp16), MUFU.TANH activations
        __half* hn = g_h16[(s + 1) & 1];
        #pragma unroll
        for (int nb = 0; nb < 2; ++nb) {
            int j = j0 + wN * 4 + nb * 2 + jA;
            float i0 = sig_mufu(zif[nb][0] + bI[nb]);
            float f0 = sig_mufu(zif[nb][1] + bF[nb]);
            float g0 = tanh_mufu(zgo[nb][0] + bG[nb]);
            float o0 = sig_mufu(zgo[nb][1] + bO[nb]);
            float i1 = sig_mufu(zif[nb][2] + bI[nb]);
            float f1 = sig_mufu(zif[nb][3] + bF[nb]);
            float g1 = tanh_mufu(zgo[nb][2] + bG[nb]);
            float o1 = sig_mufu(zgo[nb][3] + bO[nb]);
            cst[nb * 2 + 0] = f0 * cst[nb * 2 + 0] + i0 * g0;
            cst[nb * 2 + 1] = f1 * cst[nb * 2 + 1] + i1 * g1;
            hn[(size_t)(r0 + rA) * HID + j] =
                __float2half_rn(o0 * tanh_mufu(cst[nb * 2 + 0]));
            hn[(size_t)(r0 + rA + 8) * HID + j] =
                __float2half_rn(o1 * tanh_mufu(cst[nb * 2 + 1]));
        }

        // -- split barrier: arrive (release) NOW, stage x(s+1) in the window
        __syncthreads();                      // all h stores + sA reads done
        unsigned long long tick = 0;
        if (tid == 0) {
            asm volatile("atom.add.release.gpu.global.u64 %0, [%1], 1;"
                         : "=l"(tick) : "l"(bar_ctr) : "memory");
            tick += 1ULL;
        }
        if (s + 1 < SEQ) {
            const float* xp = x + ((size_t)(r0 + xrow) * SEQ + (s + 1)) * DIM + xkb;
            #pragma unroll
            for (int c2 = 0; c2 < 4; ++c2) {
                float4 v0 = *(const float4*)(xp + c2 * 8);
                float4 v1 = *(const float4*)(xp + c2 * 8 + 4);
                union { __half2 h; uint32_t u; } q0, q1, q2, q3;
                q0.h = __floats2half2_rn(v0.x, v0.y);
                q1.h = __floats2half2_rn(v0.z, v0.w);
                q2.h = __floats2half2_rn(v1.x, v1.y);
                q3.h = __floats2half2_rn(v1.z, v1.w);
                int k = xkb + c2 * 8;
                *(uint4*)(sA + a_phys(k >> 4, xrow, (k >> 3) & 1)) =
                    make_uint4(q0.u, q1.u, q2.u, q3.u);
            }
        }
        if (tid == 0) {
            unsigned long long target =
                ((tick + (unsigned long long)NGRP - 1ULL) / NGRP) *
                (unsigned long long)NGRP;
            unsigned long long v;
            do {
                asm volatile("ld.acquire.gpu.u64 %0, [%1];"
                             : "=l"(v) : "l"(bar_ctr) : "memory");
            } while (v < target);
        }
        __syncthreads();
    }

    // ---- classifier + softmax: rows are group-local ----
    if (warp < 4) {
        const int row = cta * 4 + warp;
        const __half* hf = g_h16[0];
        float acc10[10];
        #pragma unroll
        for (int c = 0; c < 10; ++c) acc10[c] = 0.f;
        uint4 hv = __ldcv((const uint4*)(hf + (size_t)row * HID + lane * 8));
        const __half* hvh = (const __half*)&hv;
        #pragma unroll
        for (int u = 0; u < 8; ++u) {
            float h = __half2float(hvh[u]);
            const float* wd = Wd + (size_t)(lane * 8 + u) * 10;
            #pragma unroll
            for (int c = 0; c < 10; ++c) acc10[c] += h * wd[c];
        }
        #pragma unroll
        for (int off = 16; off > 0; off >>= 1) {
            #pragma unroll
            for (int c = 0; c < 10; ++c)
                acc10[c] += __shfl_down_sync(0xffffffffu, acc10[c], off);
        }
        if (lane == 0) {
            float m = -3.0e38f;
            #pragma unroll
            for (int c = 0; c < 10; ++c) { acc10[c] += bd[c]; m = fmaxf(m, acc10[c]); }
            float ssum = 0.f;
            #pragma unroll
            for (int c = 0; c < 10; ++c) { acc10[c] = __expf(acc10[c] - m); ssum += acc10[c]; }
            float inv = 1.0f / ssum;
            #pragma unroll
            for (int c = 0; c < 10; ++c) out[(size_t)row * 10 + c] = acc10[c] * inv;
        }
    }
}

extern "C" void kernel_launch(void* const* d_in, const int* in_sizes, int n_in,
                              void* d_out, int out_size) {
    const float* x  = (const float*)d_in[0];
    const float* Wx = (const float*)d_in[1];
    const float* Wh = (const float*)d_in[2];
    const float* b  = (const float*)d_in[3];
    const float* Wd = (const float*)d_in[4];
    const float* bd = (const float*)d_in[5];
    (void)in_sizes; (void)n_in; (void)out_size;
    lstm_hmma<<<NCTA, NTHR>>>(x, Wx, Wh, b, Wd, bd, (float*)d_out);
}